// round 11
// baseline (speedup 1.0000x reference)
#include <cuda_runtime.h>
#include <cuda_bf16.h>
#include <stdint.h>
#include <math.h>

#define L_STEPS 512
#define BATCH   128
#define HID     512
#define DIN     512

// ---------------- device scratch ----------------
__device__ __nv_bfloat16 g_h_hi[2][BATCH * HID];
__device__ __nv_bfloat16 g_h_lo[2][BATCH * HID];
__device__ unsigned g_bar_arrive = 0;
__device__ volatile unsigned g_bar_gen = 0;
__device__ unsigned g_garr[8 * 32];
__device__ unsigned g_ggen[8 * 32];

#define SCAN_BLOCKS  64
#define SCAN_THREADS 256
#define GROUP_CTAS   8

// scan smem: Whi[64][520]bf16, Wlo, hhi[16][520]bf16, hlo
#define W_STRIDE 520
#define H_STRIDE 520
#define WS_BYTES (64 * W_STRIDE * 2)      // 66560
#define HS_BYTES (16 * H_STRIDE * 2)      // 16640
#define OFF_WHI  0
#define OFF_WLO  (WS_BYTES)
#define OFF_HHI  (2 * WS_BYTES)
#define OFF_HLO  (2 * WS_BYTES + HS_BYTES)
#define SMEM_BYTES (2 * WS_BYTES + 2 * HS_BYTES)   // 166400

// xproj smem: 4 tiles of [128][72] bf16
#define XP_STRIDE 72
#define XP_TILE_BYTES (128 * XP_STRIDE * 2)
#define XP_AHI 0
#define XP_ALO (XP_TILE_BYTES)
#define XP_BHI (2 * XP_TILE_BYTES)
#define XP_BLO (3 * XP_TILE_BYTES)
#define XP_SMEM (4 * XP_TILE_BYTES)

// ---------------- barriers ----------------
__device__ __forceinline__ void full_grid_barrier() {
    __threadfence();
    __syncthreads();
    if (threadIdx.x == 0) {
        unsigned gen = g_bar_gen;
        if (atomicAdd(&g_bar_arrive, 1u) == SCAN_BLOCKS - 1) {
            g_bar_arrive = 0;
            __threadfence();
            g_bar_gen = gen + 1;
        } else {
            while (g_bar_gen == gen) { __nanosleep(32); }
        }
    }
    __syncthreads();
}

// acq_rel group barrier (R6 semantics), 8 arrivals, tight poll (1 thread/CTA)
__device__ __forceinline__ void group_barrier(int grp) {
    __syncthreads();
    if (threadIdx.x == 0) {
        unsigned* arr = &g_garr[grp * 32];
        unsigned* gen = &g_ggen[grp * 32];
        unsigned g;
        asm volatile("ld.relaxed.gpu.u32 %0, [%1];" : "=r"(g) : "l"(gen));
        unsigned old;
        asm volatile("atom.add.acq_rel.gpu.u32 %0, [%1], 1;" : "=r"(old) : "l"(arr));
        if (old == GROUP_CTAS - 1) {
            asm volatile("st.relaxed.gpu.u32 [%0], 0;" :: "l"(arr));
            unsigned ng = g + 1;
            asm volatile("st.release.gpu.u32 [%0], %1;" :: "l"(gen), "r"(ng));
        } else {
            unsigned cur;
            do {
                asm volatile("ld.acquire.gpu.u32 %0, [%1];" : "=r"(cur) : "l"(gen));
            } while (cur == g);
        }
    }
    __syncthreads();
}

// ---------------- mma / ldmatrix helpers ----------------
__device__ __forceinline__ void mma_bf16(float* c,
                                         uint32_t a0, uint32_t a1, uint32_t a2, uint32_t a3,
                                         uint32_t b0, uint32_t b1) {
    asm volatile(
        "mma.sync.aligned.m16n8k16.row.col.f32.bf16.bf16.f32 "
        "{%0,%1,%2,%3}, {%4,%5,%6,%7}, {%8,%9}, {%0,%1,%2,%3};"
        : "+f"(c[0]), "+f"(c[1]), "+f"(c[2]), "+f"(c[3])
        : "r"(a0), "r"(a1), "r"(a2), "r"(a3), "r"(b0), "r"(b1));
}
__device__ __forceinline__ void ldsm_x4(uint32_t r[4], uint32_t addr) {
    asm volatile("ldmatrix.sync.aligned.m8n8.x4.shared.b16 {%0,%1,%2,%3}, [%4];"
                 : "=r"(r[0]), "=r"(r[1]), "=r"(r[2]), "=r"(r[3]) : "r"(addr));
}
__device__ __forceinline__ void ldsm_x2(uint32_t r[2], uint32_t addr) {
    asm volatile("ldmatrix.sync.aligned.m8n8.x2.shared.b16 {%0,%1}, [%2];"
                 : "=r"(r[0]), "=r"(r[1]) : "r"(addr));
}
__device__ __forceinline__ void split_bf16(float v, __nv_bfloat16& hi, __nv_bfloat16& lo) {
    hi = __float2bfloat16(v);
    lo = __float2bfloat16(v - __bfloat162float(hi));
}
__device__ __forceinline__ float fast_tanh(float x) {
    float e = __expf(2.0f * x);
    return 1.0f - 2.0f / (e + 1.0f);
}

// ---------------- Phase 1: xproj via bf16-split MMA (pipelined loads) ---------
__global__ void __launch_bounds__(256, 1) xproj_mma_kernel(
    const float* __restrict__ x, const float* __restrict__ Wx,
    const float* __restrict__ bx, const float* __restrict__ bh,
    float* __restrict__ out)
{
    extern __shared__ char sm[];
    __nv_bfloat16* a_hi = (__nv_bfloat16*)(sm + XP_AHI);
    __nv_bfloat16* a_lo = (__nv_bfloat16*)(sm + XP_ALO);
    __nv_bfloat16* b_hi = (__nv_bfloat16*)(sm + XP_BHI);
    __nv_bfloat16* b_lo = (__nv_bfloat16*)(sm + XP_BLO);

    const int tid  = threadIdx.x;
    const int lane = tid & 31;
    const int w    = tid >> 5;
    const int wm   = w & 3;
    const int wn   = w >> 2;
    const int m0   = blockIdx.y << 7;
    const int n0   = blockIdx.x << 7;

    const uint32_t aHiU = (uint32_t)__cvta_generic_to_shared(a_hi);
    const uint32_t aLoU = (uint32_t)__cvta_generic_to_shared(a_lo);
    const uint32_t bHiU = (uint32_t)__cvta_generic_to_shared(b_hi);
    const uint32_t bLoU = (uint32_t)__cvta_generic_to_shared(b_lo);

    const int arow   = (lane & 7) + ((lane >> 3) & 1) * 8;
    const int akoff  = (lane >> 4) * 16;
    const int bn     = ((lane >> 4) << 3) + (lane & 7);
    const int bkoff  = ((lane >> 3) & 1) * 16;

    uint32_t aHiB[2], aLoB[2];
    #pragma unroll
    for (int mi = 0; mi < 2; ++mi) {
        int r = (wm << 5) + (mi << 4) + arow;
        aHiB[mi] = aHiU + r * (XP_STRIDE * 2) + akoff;
        aLoB[mi] = aLoU + r * (XP_STRIDE * 2) + akoff;
    }

    float acc[2][8][4];
    #pragma unroll
    for (int mi = 0; mi < 2; ++mi)
        #pragma unroll
        for (int nf = 0; nf < 8; ++nf)
            #pragma unroll
            for (int r = 0; r < 4; ++r) acc[mi][nf][r] = 0.f;

    const int ldRow = tid >> 4;
    const int ldC4  = tid & 15;

    float4 avc[8], bvc[8];
    #pragma unroll
    for (int t = 0; t < 8; ++t) {
        const int row = ldRow + (t << 4);
        avc[t] = __ldg((const float4*)(x  + (size_t)(m0 + row) * DIN) + ldC4);
        bvc[t] = __ldg((const float4*)(Wx + (size_t)(n0 + row) * DIN) + ldC4);
    }

    for (int kc = 0; kc < DIN; kc += 64) {
        __syncthreads();
        #pragma unroll
        for (int t = 0; t < 8; ++t) {
            const int row = ldRow + (t << 4);
            __nv_bfloat16 h0, l0, h1, l1, h2, l2, h3, l3;
            split_bf16(avc[t].x, h0, l0); split_bf16(avc[t].y, h1, l1);
            split_bf16(avc[t].z, h2, l2); split_bf16(avc[t].w, h3, l3);
            __nv_bfloat162* pH = (__nv_bfloat162*)(a_hi + row * XP_STRIDE + (ldC4 << 2));
            __nv_bfloat162* pL = (__nv_bfloat162*)(a_lo + row * XP_STRIDE + (ldC4 << 2));
            pH[0] = __nv_bfloat162(h0, h1); pH[1] = __nv_bfloat162(h2, h3);
            pL[0] = __nv_bfloat162(l0, l1); pL[1] = __nv_bfloat162(l2, l3);
            split_bf16(bvc[t].x, h0, l0); split_bf16(bvc[t].y, h1, l1);
            split_bf16(bvc[t].z, h2, l2); split_bf16(bvc[t].w, h3, l3);
            pH = (__nv_bfloat162*)(b_hi + row * XP_STRIDE + (ldC4 << 2));
            pL = (__nv_bfloat162*)(b_lo + row * XP_STRIDE + (ldC4 << 2));
            pH[0] = __nv_bfloat162(h0, h1); pH[1] = __nv_bfloat162(h2, h3);
            pL[0] = __nv_bfloat162(l0, l1); pL[1] = __nv_bfloat162(l2, l3);
        }
        __syncthreads();

        if (kc + 64 < DIN) {
            #pragma unroll
            for (int t = 0; t < 8; ++t) {
                const int row = ldRow + (t << 4);
                avc[t] = __ldg((const float4*)(x  + (size_t)(m0 + row) * DIN + kc + 64) + ldC4);
                bvc[t] = __ldg((const float4*)(Wx + (size_t)(n0 + row) * DIN + kc + 64) + ldC4);
            }
        }

        #pragma unroll
        for (int k16 = 0; k16 < 4; ++k16) {
            const uint32_t ko = k16 * 32;
            uint32_t ah[2][4], al[2][4];
            ldsm_x4(ah[0], aHiB[0] + ko);
            ldsm_x4(ah[1], aHiB[1] + ko);
            ldsm_x4(al[0], aLoB[0] + ko);
            ldsm_x4(al[1], aLoB[1] + ko);
            #pragma unroll
            for (int np = 0; np < 4; ++np) {
                const uint32_t bOff =
                    ((wn << 6) + (np << 4) + bn) * (XP_STRIDE * 2) + bkoff + ko;
                uint32_t bh4[4], bl4[4];
                ldsm_x4(bh4, bHiU + bOff);
                ldsm_x4(bl4, bLoU + bOff);
                #pragma unroll
                for (int mi = 0; mi < 2; ++mi) {
                    #pragma unroll
                    for (int nf = 0; nf < 2; ++nf) {
                        float* c = acc[mi][(np << 1) + nf];
                        mma_bf16(c, ah[mi][0], ah[mi][1], ah[mi][2], ah[mi][3],
                                 bh4[2 * nf], bh4[2 * nf + 1]);
                        mma_bf16(c, ah[mi][0], ah[mi][1], ah[mi][2], ah[mi][3],
                                 bl4[2 * nf], bl4[2 * nf + 1]);
                        mma_bf16(c, al[mi][0], al[mi][1], al[mi][2], al[mi][3],
                                 bh4[2 * nf], bh4[2 * nf + 1]);
                    }
                }
            }
        }
    }

    const int er = lane >> 2;
    const int ec = (lane & 3) << 1;
    float bb[8][2];
    #pragma unroll
    for (int nf = 0; nf < 8; ++nf) {
        int gn = n0 + (wn << 6) + (nf << 3) + ec;
        bb[nf][0] = __ldg(bx + gn) + __ldg(bh + gn);
        bb[nf][1] = __ldg(bx + gn + 1) + __ldg(bh + gn + 1);
    }
    #pragma unroll
    for (int mi = 0; mi < 2; ++mi) {
        const int gm = m0 + (wm << 5) + (mi << 4) + er;
        #pragma unroll
        for (int nf = 0; nf < 8; ++nf) {
            const int gn = n0 + (wn << 6) + (nf << 3) + ec;
            float* c = acc[mi][nf];
            *(float2*)(out + (size_t)gm * HID + gn) =
                make_float2(c[0] + bb[nf][0], c[1] + bb[nf][1]);
            *(float2*)(out + (size_t)(gm + 8) * HID + gn) =
                make_float2(c[2] + bb[nf][0], c[3] + bb[nf][1]);
        }
    }
}

// ---------------- Phase 2: persistent scan ------------------------------------
// 64 CTAs: bt = blockIdx.x>>3 (16 batch rows), ht = blockIdx.x&7 (64 cols).
// R6 exchange (producer-side bf16 hi/lo split into g_h ping-pong), but
// 8-CTA groups and ALL 8 warps doing MMA (warp w -> cols j0+8w..j0+8w+7).
__global__ void __launch_bounds__(SCAN_THREADS, 1) rnn_scan_kernel(
    const float* __restrict__ h0, const float* __restrict__ Wh,
    float* __restrict__ out)
{
    extern __shared__ char sm[];
    __nv_bfloat16* ws_hi = (__nv_bfloat16*)(sm + OFF_WHI);
    __nv_bfloat16* ws_lo = (__nv_bfloat16*)(sm + OFF_WLO);
    __nv_bfloat16* hs_hi = (__nv_bfloat16*)(sm + OFF_HHI);
    __nv_bfloat16* hs_lo = (__nv_bfloat16*)(sm + OFF_HLO);

    const int tid  = threadIdx.x;
    const int lane = tid & 31;
    const int w    = tid >> 5;
    const int bt = blockIdx.x >> 3;
    const int ht = blockIdx.x & 7;
    const int b0 = bt << 4;        // 16 batch rows
    const int j0 = ht << 6;        // 64 output cols

    // init: split h0 into bf16 hi/lo (64*256 = 16384 threads, 1 f4 each)
    {
        int idx = blockIdx.x * SCAN_THREADS + tid;
        float4 v = __ldg((const float4*)h0 + idx);
        __nv_bfloat16 h0b, l0b, h1b, l1b, h2b, l2b, h3b, l3b;
        split_bf16(v.x, h0b, l0b); split_bf16(v.y, h1b, l1b);
        split_bf16(v.z, h2b, l2b); split_bf16(v.w, h3b, l3b);
        __nv_bfloat162* dH = (__nv_bfloat162*)(g_h_hi[0]) + idx * 2;
        __nv_bfloat162* dL = (__nv_bfloat162*)(g_h_lo[0]) + idx * 2;
        dH[0] = __nv_bfloat162(h0b, h1b); dH[1] = __nv_bfloat162(h2b, h3b);
        dL[0] = __nv_bfloat162(l0b, l1b); dL[1] = __nv_bfloat162(l2b, l3b);
    }
    // init: split W slice rows j0..j0+63 into smem [n][k]
    for (int i = tid; i < 64 * HID; i += SCAN_THREADS) {
        int n = i >> 9, k = i & 511;
        float v = __ldg(Wh + (size_t)(j0 + n) * HID + k);
        __nv_bfloat16 hi, lo;
        split_bf16(v, hi, lo);
        ws_hi[n * W_STRIDE + k] = hi;
        ws_lo[n * W_STRIDE + k] = lo;
    }
    full_grid_barrier();

    uint32_t hs_hi_u = (uint32_t)__cvta_generic_to_shared(hs_hi);
    uint32_t hs_lo_u = (uint32_t)__cvta_generic_to_shared(hs_lo);
    uint32_t ws_hi_u = (uint32_t)__cvta_generic_to_shared(ws_hi);
    uint32_t ws_lo_u = (uint32_t)__cvta_generic_to_shared(ws_lo);

    const int arow  = (lane & 7) + ((lane >> 3) & 1) * 8;
    const int akoff = (lane >> 4) * 16;
    const uint32_t aHiBase = hs_hi_u + arow * (H_STRIDE * 2) + akoff;
    const uint32_t aLoBase = hs_lo_u + arow * (H_STRIDE * 2) + akoff;
    const int brow  = 8 * w + (lane & 7);
    const int bkoff = ((lane >> 3) & 1) * 16;
    const uint32_t bHiBase = ws_hi_u + brow * (W_STRIDE * 2) + bkoff;
    const uint32_t bLoBase = ws_lo_u + brow * (W_STRIDE * 2) + bkoff;

    const int er = lane >> 2;
    const int ec = 2 * (lane & 3);
    const int jcol = j0 + 8 * w + ec;
    const size_t o1 = (size_t)(b0 + er) * HID + jcol;
    const size_t o2 = (size_t)(b0 + er + 8) * HID + jcol;

    int p = 0;

    for (int t = 0; t < L_STEPS; ++t) {
        float* gout = out + (size_t)t * (BATCH * HID);
        float2 xp1 = *(const float2*)(gout + o1);
        float2 xp2 = *(const float2*)(gout + o2);

        // stage h tile (16 rows) hi+lo into smem
        {
            const float4* srcH = (const float4*)(g_h_hi[p] + b0 * HID);
            const float4* srcL = (const float4*)(g_h_lo[p] + b0 * HID);
            float4* dH = (float4*)hs_hi;
            float4* dL = (float4*)hs_lo;
            #pragma unroll
            for (int n = 0; n < 4; ++n) {
                int i = tid + n * SCAN_THREADS;
                int row = i >> 6, c4 = i & 63;
                int d = row * 65 + c4;
                dH[d] = __ldcg(srcH + i);
                dL[d] = __ldcg(srcL + i);
            }
        }
        __syncthreads();

        float chh[4] = {0.f, 0.f, 0.f, 0.f};
        float chl[4] = {0.f, 0.f, 0.f, 0.f};
        float clh[4] = {0.f, 0.f, 0.f, 0.f};
        #pragma unroll 8
        for (int ki = 0; ki < 32; ++ki) {
            const uint32_t koff = ki * 32;
            uint32_t ah[4], al[4], bh[2], bl[2];
            ldsm_x4(ah, aHiBase + koff);
            ldsm_x4(al, aLoBase + koff);
            ldsm_x2(bh, bHiBase + koff);
            ldsm_x2(bl, bLoBase + koff);
            mma_bf16(chh, ah[0], ah[1], ah[2], ah[3], bh[0], bh[1]);
            mma_bf16(chl, ah[0], ah[1], ah[2], ah[3], bl[0], bl[1]);
            mma_bf16(clh, al[0], al[1], al[2], al[3], bh[0], bh[1]);
        }

        float hn0 = fast_tanh(chh[0] + chl[0] + clh[0] + xp1.x);
        float hn1 = fast_tanh(chh[1] + chl[1] + clh[1] + xp1.y);
        float hn2 = fast_tanh(chh[2] + chl[2] + clh[2] + xp2.x);
        float hn3 = fast_tanh(chh[3] + chl[3] + clh[3] + xp2.y);

        __nv_bfloat16 h0b, l0b, h1b, l1b, h2b, l2b, h3b, l3b;
        split_bf16(hn0, h0b, l0b);
        split_bf16(hn1, h1b, l1b);
        split_bf16(hn2, h2b, l2b);
        split_bf16(hn3, h3b, l3b);

        // publish next-step state FIRST (inter-CTA critical path)
        __nv_bfloat16* ghh = g_h_hi[p ^ 1];
        __nv_bfloat16* ghl = g_h_lo[p ^ 1];
        *(__nv_bfloat162*)(ghh + o1) = __nv_bfloat162(h0b, h1b);
        *(__nv_bfloat162*)(ghh + o2) = __nv_bfloat162(h2b, h3b);
        *(__nv_bfloat162*)(ghl + o1) = __nv_bfloat162(l0b, l1b);
        *(__nv_bfloat162*)(ghl + o2) = __nv_bfloat162(l2b, l3b);

        // hAll fp32 stores (off the critical path)
        *(float2*)(gout + o1) = make_float2(hn0, hn1);
        *(float2*)(gout + o2) = make_float2(hn2, hn3);

        if (t == L_STEPS - 1) {
            float* hlast = out + (size_t)L_STEPS * BATCH * HID;
            *(float2*)(hlast + o1) = make_float2(hn0, hn1);
            *(float2*)(hlast + o2) = make_float2(hn2, hn3);
        } else {
            group_barrier(bt);
        }
        p ^= 1;
    }
}

// ---------------- launch -------------------------------------------------------
extern "C" void kernel_launch(void* const* d_in, const int* in_sizes, int n_in,
                              void* d_out, int out_size)
{
    const float* x   = (const float*)d_in[0];
    const float* h0  = (const float*)d_in[1];
    const float* Wxw = (const float*)d_in[2];
    const float* Wxb = (const float*)d_in[3];
    const float* Whw = (const float*)d_in[4];
    const float* Whb = (const float*)d_in[5];
    float* out = (float*)d_out;

    cudaFuncSetAttribute(xproj_mma_kernel,
                         cudaFuncAttributeMaxDynamicSharedMemorySize, XP_SMEM);
    dim3 g1(HID / 128, (L_STEPS * BATCH) / 128);
    xproj_mma_kernel<<<g1, 256, XP_SMEM>>>(x, Wxw, Wxb, Whb, out);

    cudaFuncSetAttribute(rnn_scan_kernel,
                         cudaFuncAttributeMaxDynamicSharedMemorySize, SMEM_BYTES);
    rnn_scan_kernel<<<SCAN_BLOCKS, SCAN_THREADS, SMEM_BYTES>>>(h0, Whw, out);
}

// round 12
// speedup vs baseline: 1.2685x; 1.2685x over previous
#include <cuda_runtime.h>
#include <cuda_bf16.h>
#include <stdint.h>
#include <math.h>

#define L_STEPS 512
#define BATCH   128
#define HID     512
#define DIN     512

// ---------------- device scratch ----------------
__device__ __nv_bfloat16 g_h_hi[2][BATCH * HID];
__device__ __nv_bfloat16 g_h_lo[2][BATCH * HID];
__device__ __nv_bfloat16 g_wx_hi[DIN * HID];
__device__ __nv_bfloat16 g_wx_lo[DIN * HID];
__device__ unsigned g_bar_arrive = 0;
__device__ volatile unsigned g_bar_gen = 0;
__device__ unsigned g_garr[8 * 32];
__device__ unsigned g_ggen[8 * 32];

#define SCAN_BLOCKS  128
#define SCAN_THREADS 256

// scan smem: Whi[32][520]bf16, Wlo, hhi[16][520]bf16, hlo
#define W_STRIDE 520
#define H_STRIDE 520
#define WS_BYTES (32 * W_STRIDE * 2)
#define HS_BYTES (16 * H_STRIDE * 2)
#define OFF_WHI  0
#define OFF_WLO  (WS_BYTES)
#define OFF_HHI  (2 * WS_BYTES)
#define OFF_HLO  (2 * WS_BYTES + HS_BYTES)
#define SMEM_BYTES (2 * WS_BYTES + 2 * HS_BYTES)

// xproj smem: 4 tiles of [128][72] bf16
#define XP_STRIDE 72
#define XP_TILE_BYTES (128 * XP_STRIDE * 2)
#define XP_AHI 0
#define XP_ALO (XP_TILE_BYTES)
#define XP_BHI (2 * XP_TILE_BYTES)
#define XP_BLO (3 * XP_TILE_BYTES)
#define XP_SMEM (4 * XP_TILE_BYTES)

// ---------------- barriers ----------------
__device__ __forceinline__ void full_grid_barrier() {
    __threadfence();
    __syncthreads();
    if (threadIdx.x == 0) {
        unsigned gen = g_bar_gen;
        if (atomicAdd(&g_bar_arrive, 1u) == SCAN_BLOCKS - 1) {
            g_bar_arrive = 0;
            __threadfence();
            g_bar_gen = gen + 1;
        } else {
            while (g_bar_gen == gen) { __nanosleep(32); }
        }
    }
    __syncthreads();
}

// acq_rel group barrier: 16 CTAs of the same bt group (R6 — proven best)
__device__ __forceinline__ void group_barrier(int grp) {
    __syncthreads();
    if (threadIdx.x == 0) {
        unsigned* arr = &g_garr[grp * 32];
        unsigned* gen = &g_ggen[grp * 32];
        unsigned g;
        asm volatile("ld.relaxed.gpu.u32 %0, [%1];" : "=r"(g) : "l"(gen));
        unsigned old;
        asm volatile("atom.add.acq_rel.gpu.u32 %0, [%1], 1;" : "=r"(old) : "l"(arr));
        if (old == 15) {
            asm volatile("st.relaxed.gpu.u32 [%0], 0;" :: "l"(arr));
            unsigned ng = g + 1;
            asm volatile("st.release.gpu.u32 [%0], %1;" :: "l"(gen), "r"(ng));
        } else {
            unsigned cur;
            do {
                __nanosleep(20);
                asm volatile("ld.acquire.gpu.u32 %0, [%1];" : "=r"(cur) : "l"(gen));
            } while (cur == g);
        }
    }
    __syncthreads();
}

// named barrier producer/consumer handoff (chunked staging)
#define NB_ARRIVE(id) asm volatile("bar.arrive %0, 256;" :: "r"(id) : "memory")
#define NB_SYNC(id)   asm volatile("bar.sync %0, 256;"   :: "r"(id) : "memory")

// ---------------- mma / ldmatrix helpers ----------------
__device__ __forceinline__ void mma_bf16(float* c,
                                         uint32_t a0, uint32_t a1, uint32_t a2, uint32_t a3,
                                         uint32_t b0, uint32_t b1) {
    asm volatile(
        "mma.sync.aligned.m16n8k16.row.col.f32.bf16.bf16.f32 "
        "{%0,%1,%2,%3}, {%4,%5,%6,%7}, {%8,%9}, {%0,%1,%2,%3};"
        : "+f"(c[0]), "+f"(c[1]), "+f"(c[2]), "+f"(c[3])
        : "r"(a0), "r"(a1), "r"(a2), "r"(a3), "r"(b0), "r"(b1));
}
__device__ __forceinline__ void ldsm_x4(uint32_t r[4], uint32_t addr) {
    asm volatile("ldmatrix.sync.aligned.m8n8.x4.shared.b16 {%0,%1,%2,%3}, [%4];"
                 : "=r"(r[0]), "=r"(r[1]), "=r"(r[2]), "=r"(r[3]) : "r"(addr));
}
__device__ __forceinline__ void ldsm_x2(uint32_t r[2], uint32_t addr) {
    asm volatile("ldmatrix.sync.aligned.m8n8.x2.shared.b16 {%0,%1}, [%2];"
                 : "=r"(r[0]), "=r"(r[1]) : "r"(addr));
}
__device__ __forceinline__ void split_bf16(float v, __nv_bfloat16& hi, __nv_bfloat16& lo) {
    hi = __float2bfloat16(v);
    lo = __float2bfloat16(v - __bfloat162float(hi));
}
__device__ __forceinline__ float fast_tanh(float x) {
    float e = __expf(2.0f * x);
    return 1.0f - 2.0f / (e + 1.0f);
}

// ---------------- Phase 0: pre-split Wx into bf16 hi/lo -----------------------
__global__ void __launch_bounds__(512) wx_split_kernel(const float* __restrict__ Wx) {
    int idx = blockIdx.x * 512 + threadIdx.x;     // 65536 f4 total
    float4 v = __ldg((const float4*)Wx + idx);
    __nv_bfloat16 h0, l0, h1, l1, h2, l2, h3, l3;
    split_bf16(v.x, h0, l0); split_bf16(v.y, h1, l1);
    split_bf16(v.z, h2, l2); split_bf16(v.w, h3, l3);
    __nv_bfloat162* dH = (__nv_bfloat162*)g_wx_hi + idx * 2;
    __nv_bfloat162* dL = (__nv_bfloat162*)g_wx_lo + idx * 2;
    dH[0] = __nv_bfloat162(h0, h1); dH[1] = __nv_bfloat162(h2, h3);
    dL[0] = __nv_bfloat162(l0, l1); dL[1] = __nv_bfloat162(l2, l3);
}

// ---------------- Phase 1: xproj via bf16-split MMA ---------------------------
// A (x) converted on the fly (pipelined); B (Wx) read pre-split in bf16.
__global__ void __launch_bounds__(256, 1) xproj_mma_kernel(
    const float* __restrict__ x,
    const float* __restrict__ bx, const float* __restrict__ bh,
    float* __restrict__ out)
{
    extern __shared__ char sm[];
    __nv_bfloat16* a_hi = (__nv_bfloat16*)(sm + XP_AHI);
    __nv_bfloat16* a_lo = (__nv_bfloat16*)(sm + XP_ALO);
    __nv_bfloat16* b_hi = (__nv_bfloat16*)(sm + XP_BHI);
    __nv_bfloat16* b_lo = (__nv_bfloat16*)(sm + XP_BLO);

    const int tid  = threadIdx.x;
    const int lane = tid & 31;
    const int w    = tid >> 5;
    const int wm   = w & 3;
    const int wn   = w >> 2;
    const int m0   = blockIdx.y << 7;
    const int n0   = blockIdx.x << 7;

    const uint32_t aHiU = (uint32_t)__cvta_generic_to_shared(a_hi);
    const uint32_t aLoU = (uint32_t)__cvta_generic_to_shared(a_lo);
    const uint32_t bHiU = (uint32_t)__cvta_generic_to_shared(b_hi);
    const uint32_t bLoU = (uint32_t)__cvta_generic_to_shared(b_lo);

    const int arow   = (lane & 7) + ((lane >> 3) & 1) * 8;
    const int akoff  = (lane >> 4) * 16;
    const int bn     = ((lane >> 4) << 3) + (lane & 7);
    const int bkoff  = ((lane >> 3) & 1) * 16;

    uint32_t aHiB[2], aLoB[2];
    #pragma unroll
    for (int mi = 0; mi < 2; ++mi) {
        int r = (wm << 5) + (mi << 4) + arow;
        aHiB[mi] = aHiU + r * (XP_STRIDE * 2) + akoff;
        aLoB[mi] = aLoU + r * (XP_STRIDE * 2) + akoff;
    }

    float acc[2][8][4];
    #pragma unroll
    for (int mi = 0; mi < 2; ++mi)
        #pragma unroll
        for (int nf = 0; nf < 8; ++nf)
            #pragma unroll
            for (int r = 0; r < 4; ++r) acc[mi][nf][r] = 0.f;

    const int ldRow = tid >> 4;        // 0..15
    const int ldC4  = tid & 15;        // A: f4-of-fp32 col in 64-chunk
    // B loader mapping: 1024 f4(bf16) per tile, 4 per thread
    // i = tid + n*256: brow = i>>3, bc8 = i&7 ; dest f4 = brow*9 + bc8
    // src f4 = (n0+brow)*64 + (kc>>3) + bc8

    // prefetch A chunk 0
    float4 avc[8];
    #pragma unroll
    for (int t = 0; t < 8; ++t) {
        const int row = ldRow + (t << 4);
        avc[t] = __ldg((const float4*)(x + (size_t)(m0 + row) * DIN) + ldC4);
    }

    for (int kc = 0; kc < DIN; kc += 64) {
        __syncthreads();
        // B tiles: direct bf16 copy (loads issued first for MLP)
        float4 bhv[4], blv[4];
        #pragma unroll
        for (int n = 0; n < 4; ++n) {
            const int i = tid + (n << 8);
            const int brow = i >> 3, bc8 = i & 7;
            const int src = (n0 + brow) * 64 + (kc >> 3) + bc8;
            bhv[n] = __ldg((const float4*)g_wx_hi + src);
            blv[n] = __ldg((const float4*)g_wx_lo + src);
        }
        // A conversion stores
        #pragma unroll
        for (int t = 0; t < 8; ++t) {
            const int row = ldRow + (t << 4);
            __nv_bfloat16 h0, l0, h1, l1, h2, l2, h3, l3;
            split_bf16(avc[t].x, h0, l0); split_bf16(avc[t].y, h1, l1);
            split_bf16(avc[t].z, h2, l2); split_bf16(avc[t].w, h3, l3);
            __nv_bfloat162* pH = (__nv_bfloat162*)(a_hi + row * XP_STRIDE + (ldC4 << 2));
            __nv_bfloat162* pL = (__nv_bfloat162*)(a_lo + row * XP_STRIDE + (ldC4 << 2));
            pH[0] = __nv_bfloat162(h0, h1); pH[1] = __nv_bfloat162(h2, h3);
            pL[0] = __nv_bfloat162(l0, l1); pL[1] = __nv_bfloat162(l2, l3);
        }
        // B stores (f4 of bf16; stride 72 bf16 = 9 f4)
        #pragma unroll
        for (int n = 0; n < 4; ++n) {
            const int i = tid + (n << 8);
            const int brow = i >> 3, bc8 = i & 7;
            ((float4*)b_hi)[brow * 9 + bc8] = bhv[n];
            ((float4*)b_lo)[brow * 9 + bc8] = blv[n];
        }
        __syncthreads();

        // prefetch next A chunk (overlaps MMA)
        if (kc + 64 < DIN) {
            #pragma unroll
            for (int t = 0; t < 8; ++t) {
                const int row = ldRow + (t << 4);
                avc[t] = __ldg((const float4*)(x + (size_t)(m0 + row) * DIN + kc + 64) + ldC4);
            }
        }

        #pragma unroll
        for (int k16 = 0; k16 < 4; ++k16) {
            const uint32_t ko = k16 * 32;
            uint32_t ah[2][4], al[2][4];
            ldsm_x4(ah[0], aHiB[0] + ko);
            ldsm_x4(ah[1], aHiB[1] + ko);
            ldsm_x4(al[0], aLoB[0] + ko);
            ldsm_x4(al[1], aLoB[1] + ko);
            #pragma unroll
            for (int np = 0; np < 4; ++np) {
                const uint32_t bOff =
                    ((wn << 6) + (np << 4) + bn) * (XP_STRIDE * 2) + bkoff + ko;
                uint32_t bh4[4], bl4[4];
                ldsm_x4(bh4, bHiU + bOff);
                ldsm_x4(bl4, bLoU + bOff);
                #pragma unroll
                for (int mi = 0; mi < 2; ++mi) {
                    #pragma unroll
                    for (int nf = 0; nf < 2; ++nf) {
                        float* c = acc[mi][(np << 1) + nf];
                        mma_bf16(c, ah[mi][0], ah[mi][1], ah[mi][2], ah[mi][3],
                                 bh4[2 * nf], bh4[2 * nf + 1]);
                        mma_bf16(c, ah[mi][0], ah[mi][1], ah[mi][2], ah[mi][3],
                                 bl4[2 * nf], bl4[2 * nf + 1]);
                        mma_bf16(c, al[mi][0], al[mi][1], al[mi][2], al[mi][3],
                                 bh4[2 * nf], bh4[2 * nf + 1]);
                    }
                }
            }
        }
    }

    const int er = lane >> 2;
    const int ec = (lane & 3) << 1;
    float bb[8][2];
    #pragma unroll
    for (int nf = 0; nf < 8; ++nf) {
        int gn = n0 + (wn << 6) + (nf << 3) + ec;
        bb[nf][0] = __ldg(bx + gn) + __ldg(bh + gn);
        bb[nf][1] = __ldg(bx + gn + 1) + __ldg(bh + gn + 1);
    }
    #pragma unroll
    for (int mi = 0; mi < 2; ++mi) {
        const int gm = m0 + (wm << 5) + (mi << 4) + er;
        #pragma unroll
        for (int nf = 0; nf < 8; ++nf) {
            const int gn = n0 + (wn << 6) + (nf << 3) + ec;
            float* c = acc[mi][nf];
            *(float2*)(out + (size_t)gm * HID + gn) =
                make_float2(c[0] + bb[nf][0], c[1] + bb[nf][1]);
            *(float2*)(out + (size_t)(gm + 8) * HID + gn) =
                make_float2(c[2] + bb[nf][0], c[3] + bb[nf][1]);
        }
    }
}

// ---------------- Phase 2: persistent scan (R6 + chunked staging overlap) -----
__global__ void __launch_bounds__(SCAN_THREADS, 1) rnn_scan_kernel(
    const float* __restrict__ h0, const float* __restrict__ Wh,
    float* __restrict__ out)
{
    extern __shared__ char sm[];
    __nv_bfloat16* ws_hi = (__nv_bfloat16*)(sm + OFF_WHI);
    __nv_bfloat16* ws_lo = (__nv_bfloat16*)(sm + OFF_WLO);
    __nv_bfloat16* hs_hi = (__nv_bfloat16*)(sm + OFF_HHI);
    __nv_bfloat16* hs_lo = (__nv_bfloat16*)(sm + OFF_HLO);

    const int tid  = threadIdx.x;
    const int lane = tid & 31;
    const int w    = tid >> 5;
    const int bt = blockIdx.x >> 4;
    const int ht = blockIdx.x & 15;
    const int b0 = bt << 4;
    const int j0 = ht << 5;

    // init: split h0 into bf16 hi/lo
    {
        int gtid = blockIdx.x * SCAN_THREADS + tid;
        #pragma unroll
        for (int r = 0; r < 2; ++r) {
            int i = gtid + r * (SCAN_BLOCKS * SCAN_THREADS);
            float v = __ldg(h0 + i);
            __nv_bfloat16 hi, lo;
            split_bf16(v, hi, lo);
            g_h_hi[0][i] = hi;
            g_h_lo[0][i] = lo;
        }
    }
    // init: split W slice rows j0..j0+31 into smem [n][k]
    for (int i = tid; i < 32 * HID; i += SCAN_THREADS) {
        int n = i >> 9, k = i & 511;
        float v = __ldg(Wh + (size_t)(j0 + n) * HID + k);
        __nv_bfloat16 hi, lo;
        split_bf16(v, hi, lo);
        ws_hi[n * W_STRIDE + k] = hi;
        ws_lo[n * W_STRIDE + k] = lo;
    }
    full_grid_barrier();

    uint32_t hs_hi_u = (uint32_t)__cvta_generic_to_shared(hs_hi);
    uint32_t hs_lo_u = (uint32_t)__cvta_generic_to_shared(hs_lo);
    uint32_t ws_hi_u = (uint32_t)__cvta_generic_to_shared(ws_hi);
    uint32_t ws_lo_u = (uint32_t)__cvta_generic_to_shared(ws_lo);

    const int arow  = (lane & 7) + ((lane >> 3) & 1) * 8;
    const int akoff = (lane >> 4) * 16;
    const uint32_t aHiBase = hs_hi_u + arow * (H_STRIDE * 2) + akoff;
    const uint32_t aLoBase = hs_lo_u + arow * (H_STRIDE * 2) + akoff;
    const int brow  = 8 * w + (lane & 7);
    const int bkoff = ((lane >> 3) & 1) * 16;
    const uint32_t bHiBase = ws_hi_u + brow * (W_STRIDE * 2) + bkoff;
    const uint32_t bLoBase = ws_lo_u + brow * (W_STRIDE * 2) + bkoff;

    const int er = lane >> 2;
    const int ec = 2 * (lane & 3);
    const int jcol = j0 + 8 * w + ec;
    const size_t o1 = (size_t)(b0 + er) * HID + jcol;
    const size_t o2 = (size_t)(b0 + er + 8) * HID + jcol;

    // chunk0 staging indices (all 256 threads, 2 f4 each per buffer):
    //   i in {tid, tid+256}: row = i>>5, c4 = i&31 (cols 0..255)
    // chunk1 staging indices (warps 4-7, local = tid-128, 4 f4 each per buffer):
    //   i = local + n*128: row = i>>5, c4 = 32 + (i&31) (cols 256..511)
    int p = 0;

    for (int t = 0; t < L_STEPS; ++t) {
        float* gout = out + (size_t)t * (BATCH * HID);
        float2 xp1, xp2;
        if (w < 4) {
            xp1 = *(const float2*)(gout + o1);
            xp2 = *(const float2*)(gout + o2);
        }

        const float4* srcH = (const float4*)(g_h_hi[p] + b0 * HID);
        const float4* srcL = (const float4*)(g_h_lo[p] + b0 * HID);
        float4* dH = (float4*)hs_hi;
        float4* dL = (float4*)hs_lo;

        // stage chunk0 (cols 0..255): all warps
        #pragma unroll
        for (int n = 0; n < 2; ++n) {
            int i = tid + (n << 8);
            int row = i >> 5, c4 = i & 31;
            int s = row * 64 + c4;
            int d = row * 65 + c4;
            dH[d] = __ldcg(srcH + s);
            dL[d] = __ldcg(srcL + s);
        }
        __syncthreads();

        if (w < 4) {
            float chh[4] = {0.f, 0.f, 0.f, 0.f};
            float chl[4] = {0.f, 0.f, 0.f, 0.f};
            float clh[4] = {0.f, 0.f, 0.f, 0.f};

            // chunk0 MMA: k-iters 0..15 (overlaps warps 4-7 staging chunk1)
            #pragma unroll 8
            for (int ki = 0; ki < 16; ++ki) {
                const uint32_t koff = ki * 32;
                uint32_t ah[4], al[4], bh[2], bl[2];
                ldsm_x4(ah, aHiBase + koff);
                ldsm_x4(al, aLoBase + koff);
                ldsm_x2(bh, bHiBase + koff);
                ldsm_x2(bl, bLoBase + koff);
                mma_bf16(chh, ah[0], ah[1], ah[2], ah[3], bh[0], bh[1]);
                mma_bf16(chl, ah[0], ah[1], ah[2], ah[3], bl[0], bl[1]);
                mma_bf16(clh, al[0], al[1], al[2], al[3], bh[0], bh[1]);
            }

            NB_SYNC(1);   // wait for chunk1 staged

            #pragma unroll 8
            for (int ki = 16; ki < 32; ++ki) {
                const uint32_t koff = ki * 32;
                uint32_t ah[4], al[4], bh[2], bl[2];
                ldsm_x4(ah, aHiBase + koff);
                ldsm_x4(al, aLoBase + koff);
                ldsm_x2(bh, bHiBase + koff);
                ldsm_x2(bl, bLoBase + koff);
                mma_bf16(chh, ah[0], ah[1], ah[2], ah[3], bh[0], bh[1]);
                mma_bf16(chl, ah[0], ah[1], ah[2], ah[3], bl[0], bl[1]);
                mma_bf16(clh, al[0], al[1], al[2], al[3], bh[0], bh[1]);
            }

            float hn0 = fast_tanh(chh[0] + chl[0] + clh[0] + xp1.x);
            float hn1 = fast_tanh(chh[1] + chl[1] + clh[1] + xp1.y);
            float hn2 = fast_tanh(chh[2] + chl[2] + clh[2] + xp2.x);
            float hn3 = fast_tanh(chh[3] + chl[3] + clh[3] + xp2.y);

            __nv_bfloat16 h0b, l0b, h1b, l1b, h2b, l2b, h3b, l3b;
            split_bf16(hn0, h0b, l0b);
            split_bf16(hn1, h1b, l1b);
            split_bf16(hn2, h2b, l2b);
            split_bf16(hn3, h3b, l3b);

            // publish next-step state FIRST (inter-CTA critical path)
            __nv_bfloat16* ghh = g_h_hi[p ^ 1];
            __nv_bfloat16* ghl = g_h_lo[p ^ 1];
            *(__nv_bfloat162*)(ghh + o1) = __nv_bfloat162(h0b, h1b);
            *(__nv_bfloat162*)(ghh + o2) = __nv_bfloat162(h2b, h3b);
            *(__nv_bfloat162*)(ghl + o1) = __nv_bfloat162(l0b, l1b);
            *(__nv_bfloat162*)(ghl + o2) = __nv_bfloat162(l2b, l3b);

            // hAll fp32 stores (off the critical path)
            *(float2*)(gout + o1) = make_float2(hn0, hn1);
            *(float2*)(gout + o2) = make_float2(hn2, hn3);

            if (t == L_STEPS - 1) {
                float* hlast = out + (size_t)L_STEPS * BATCH * HID;
                *(float2*)(hlast + o1) = make_float2(hn0, hn1);
                *(float2*)(hlast + o2) = make_float2(hn2, hn3);
            }
        } else {
            // warps 4-7: stage chunk1 (cols 256..511) while MMA warps compute
            const int local = tid - 128;
            #pragma unroll
            for (int n = 0; n < 4; ++n) {
                int i = local + (n << 7);
                int row = i >> 5, c4 = 32 + (i & 31);
                int s = row * 64 + c4;
                int d = row * 65 + c4;
                dH[d] = __ldcg(srcH + s);
                dL[d] = __ldcg(srcL + s);
            }
            NB_ARRIVE(1);
        }

        if (t != L_STEPS - 1) group_barrier(bt);
        p ^= 1;
    }
}

// ---------------- launch -------------------------------------------------------
extern "C" void kernel_launch(void* const* d_in, const int* in_sizes, int n_in,
                              void* d_out, int out_size)
{
    const float* x   = (const float*)d_in[0];
    const float* h0  = (const float*)d_in[1];
    const float* Wxw = (const float*)d_in[2];
    const float* Wxb = (const float*)d_in[3];
    const float* Whw = (const float*)d_in[4];
    const float* Whb = (const float*)d_in[5];
    float* out = (float*)d_out;

    wx_split_kernel<<<128, 512>>>(Wxw);

    cudaFuncSetAttribute(xproj_mma_kernel,
                         cudaFuncAttributeMaxDynamicSharedMemorySize, XP_SMEM);
    dim3 g1(HID / 128, (L_STEPS * BATCH) / 128);
    xproj_mma_kernel<<<g1, 256, XP_SMEM>>>(x, Wxb, Whb, out);

    cudaFuncSetAttribute(rnn_scan_kernel,
                         cudaFuncAttributeMaxDynamicSharedMemorySize, SMEM_BYTES);
    rnn_scan_kernel<<<SCAN_BLOCKS, SCAN_THREADS, SMEM_BYTES>>>(h0, Whw, out);
}